// round 1
// baseline (speedup 1.0000x reference)
#include <cuda_runtime.h>

#define BATCH 32
#define HH    56
#define WIMG  56
#define WS    7
#define SHIFT 3
#define NH    8
#define EMB   256
#define HD    32
#define NWIN  64
#define WD    49
#define NTOK  (HH * WIMG)   // 3136

// Scratch for attention output in (B, token, E) layout (reverse-shift already applied).
__device__ float g_mid[(size_t)BATCH * NTOK * EMB];

// ---------------------------------------------------------------------------
// Kernel 1: fused shifted-window attention.
// One block per (batch, window, head). 16384 blocks x 256 threads.
// ---------------------------------------------------------------------------
__global__ __launch_bounds__(256) void attn_kernel(
    const float* __restrict__ x,
    const float* __restrict__ qkv_w,   // (HD, 3*HD) = (32, 96)
    const float* __restrict__ qkv_b,   // (96,)
    const float* __restrict__ rpb)     // (169, NH)
{
    const int blk = blockIdx.x;
    const int h  = blk & 7;           // head
    const int w  = (blk >> 3) & 63;   // window
    const int b  = blk >> 9;          // batch
    const int wh = w >> 3;            // window row  (W/WS = 8)
    const int wc = w & 7;             // window col

    __shared__ float sx[WD][HD];        // 49 x 32 input slice
    __shared__ float swt[HD][3 * HD];   // 32 x 96 qkv weight
    __shared__ float sbias[3 * HD];
    __shared__ float sqkv[WD][97];      // 49 x 96 (+1 pad; 96%32==0 would conflict)
    __shared__ float ssc[WD][50];       // scores / attn, padded

    const int tid = threadIdx.x;

    // ---- load x head slice (fused cyclic shift + window partition) ----
    for (int i = tid; i < WD * HD; i += 256) {
        const int t = i >> 5, d = i & 31;
        const int tr = t / WS, tcl = t % WS;
        const int gr = (wh * WS + tr + SHIFT) % HH;
        const int gc = (wc * WS + tcl + SHIFT) % WIMG;
        sx[t][d] = x[((size_t)b * NTOK + gr * WIMG + gc) * EMB + h * HD + d];
    }
    for (int i = tid; i < HD * 3 * HD; i += 256)
        swt[i / 96][i % 96] = qkv_w[i];
    if (tid < 96) sbias[tid] = qkv_b[tid];
    __syncthreads();

    // ---- qkv = sx @ swt + bias  (49 x 96) ----
    for (int i = tid; i < WD * 96; i += 256) {
        const int t = i / 96, c = i % 96;
        float s = sbias[c];
#pragma unroll
        for (int k = 0; k < HD; k++) s += sx[t][k] * swt[k][c];
        sqkv[t][c] = s;
    }
    __syncthreads();

    // ---- scores = q @ k^T / sqrt(HD) + rel-pos bias + shift mask ----
    const float scale = 0.17677669529663687f;   // 1/sqrt(32)
    for (int i = tid; i < WD * WD; i += 256) {
        const int q = i / WD, kk = i % WD;
        float s = 0.f;
#pragma unroll
        for (int d = 0; d < HD; d++) s += sqkv[q][d] * sqkv[kk][HD + d];
        s *= scale;

        const int qr = q / WS, qc = q % WS;
        const int kr = kk / WS, kc = kk % WS;
        // relative position bias
        const int ridx = (qr - kr + WS - 1) * (2 * WS - 1) + (qc - kc + WS - 1);
        s += rpb[ridx * NH + h];
        // shifted-window mask: region ids on the SHIFTED grid
        const int qi = wh * WS + qr, qj = wc * WS + qc;
        const int ki = wh * WS + kr, kj = wc * WS + kc;
        const int rq = (qi < HH - WS ? 0 : (qi < HH - SHIFT ? 1 : 2)) * 3 +
                       (qj < WIMG - WS ? 0 : (qj < WIMG - SHIFT ? 1 : 2));
        const int rk = (ki < HH - WS ? 0 : (ki < HH - SHIFT ? 1 : 2)) * 3 +
                       (kj < WIMG - WS ? 0 : (kj < WIMG - SHIFT ? 1 : 2));
        if (rq != rk) s -= 100.f;
        ssc[q][kk] = s;
    }
    __syncthreads();

    // ---- softmax over rows (49 rows, one thread per row) ----
    if (tid < WD) {
        float m = -1e30f;
        for (int kk = 0; kk < WD; kk++) m = fmaxf(m, ssc[tid][kk]);
        float sum = 0.f;
        for (int kk = 0; kk < WD; kk++) {
            const float e = __expf(ssc[tid][kk] - m);
            ssc[tid][kk] = e;
            sum += e;
        }
        const float inv = 1.f / sum;
        for (int kk = 0; kk < WD; kk++) ssc[tid][kk] *= inv;
    }
    __syncthreads();

    // ---- o = attn @ v; fused reverse window partition + reverse shift ----
    for (int i = tid; i < WD * HD; i += 256) {
        const int t = i >> 5, d = i & 31;
        float s = 0.f;
#pragma unroll
        for (int kk = 0; kk < WD; kk++) s += ssc[t][kk] * sqkv[kk][2 * HD + d];
        const int tr = t / WS, tcl = t % WS;
        const int gr = (wh * WS + tr + SHIFT) % HH;
        const int gc = (wc * WS + tcl + SHIFT) % WIMG;
        g_mid[((size_t)b * NTOK + gr * WIMG + gc) * EMB + h * HD + d] = s;
    }
}

// ---------------------------------------------------------------------------
// Kernel 2: output projection. out = g_mid @ proj_w + proj_b
// M = 100352, N = K = 256. Tiled 64x64x32, 256 threads, 4x4 register tile.
// ---------------------------------------------------------------------------
__global__ __launch_bounds__(256) void proj_kernel(
    const float* __restrict__ Wp,     // (256, 256)
    const float* __restrict__ bias,   // (256,)
    float* __restrict__ out)
{
    __shared__ float As[64][33];   // pad to 33 to avoid 2-way broadcast conflicts
    __shared__ float Bs[32][64];

    const int m0 = blockIdx.y * 64;
    const int n0 = blockIdx.x * 64;
    const int tid = threadIdx.x;
    const int ty = tid >> 4, tx = tid & 15;

    float acc[4][4] = {};

    const float* __restrict__ A = g_mid;

    for (int k0 = 0; k0 < EMB; k0 += 32) {
        for (int i = tid; i < 64 * 32; i += 256) {
            const int r = i >> 5, c = i & 31;
            As[r][c] = A[(size_t)(m0 + r) * EMB + k0 + c];
        }
        for (int i = tid; i < 32 * 64; i += 256) {
            const int r = i >> 6, c = i & 63;
            Bs[r][c] = Wp[(k0 + r) * EMB + n0 + c];
        }
        __syncthreads();
#pragma unroll
        for (int k = 0; k < 32; k++) {
            const float a0 = As[ty * 4 + 0][k];
            const float a1 = As[ty * 4 + 1][k];
            const float a2 = As[ty * 4 + 2][k];
            const float a3 = As[ty * 4 + 3][k];
            const float4 bv = *(const float4*)&Bs[k][tx * 4];
            acc[0][0] += a0 * bv.x; acc[0][1] += a0 * bv.y; acc[0][2] += a0 * bv.z; acc[0][3] += a0 * bv.w;
            acc[1][0] += a1 * bv.x; acc[1][1] += a1 * bv.y; acc[1][2] += a1 * bv.z; acc[1][3] += a1 * bv.w;
            acc[2][0] += a2 * bv.x; acc[2][1] += a2 * bv.y; acc[2][2] += a2 * bv.z; acc[2][3] += a2 * bv.w;
            acc[3][0] += a3 * bv.x; acc[3][1] += a3 * bv.y; acc[3][2] += a3 * bv.z; acc[3][3] += a3 * bv.w;
        }
        __syncthreads();
    }

    const float4 bb = *(const float4*)&bias[n0 + tx * 4];
#pragma unroll
    for (int i = 0; i < 4; i++) {
        float4 o;
        o.x = acc[i][0] + bb.x;
        o.y = acc[i][1] + bb.y;
        o.z = acc[i][2] + bb.z;
        o.w = acc[i][3] + bb.w;
        *(float4*)&out[(size_t)(m0 + ty * 4 + i) * EMB + n0 + tx * 4] = o;
    }
}

// ---------------------------------------------------------------------------
extern "C" void kernel_launch(void* const* d_in, const int* in_sizes, int n_in,
                              void* d_out, int out_size)
{
    const float* x      = (const float*)d_in[0];
    const float* qkv_w  = (const float*)d_in[1];
    const float* qkv_b  = (const float*)d_in[2];
    const float* proj_w = (const float*)d_in[3];
    const float* proj_b = (const float*)d_in[4];
    const float* rpb    = (const float*)d_in[5];
    float* out = (float*)d_out;

    attn_kernel<<<BATCH * NWIN * NH, 256>>>(x, qkv_w, qkv_b, rpb);

    dim3 grid(EMB / 64, (BATCH * NTOK) / 64);   // (4, 1568)
    proj_kernel<<<grid, 256>>>(proj_w, proj_b, out);
}

// round 2
// speedup vs baseline: 1.3969x; 1.3969x over previous
#include <cuda_runtime.h>

#define BATCH 32
#define HH    56
#define WIMG  56
#define WS    7
#define SHIFT 3
#define NH    8
#define EMB   256
#define HD    32
#define NWIN  64
#define WD    49
#define NTOK  (HH * WIMG)   // 3136

// Scratch for attention output in (B, token, E) layout (reverse-shift already applied).
__device__ float g_mid[(size_t)BATCH * NTOK * EMB];

// ---------------------------------------------------------------------------
// Kernel 1: fused shifted-window attention, register-tiled.
// One block per (batch, window, head). 16384 blocks x 256 threads.
// ---------------------------------------------------------------------------
__global__ __launch_bounds__(256) void attn_kernel(
    const float* __restrict__ x,
    const float* __restrict__ qkv_w,   // (HD, 3*HD) = (32, 96)
    const float* __restrict__ qkv_b,   // (96,)
    const float* __restrict__ rpb)     // (169, NH)
{
    const int blk = blockIdx.x;
    const int h  = blk & 7;           // head
    const int w  = (blk >> 3) & 63;   // window
    const int b  = blk >> 9;          // batch
    const int wh = w >> 3;            // window row  (W/WS = 8)
    const int wc = w & 7;             // window col

    // Unioned buffer: [sx 49x32 | swt 32x96] reused later as [ssc 49x52]
    __shared__ float sbuf[4640];
    float (*sx)[HD]      = (float(*)[HD])sbuf;              // 1568 floats
    float (*swt)[96]     = (float(*)[96])(sbuf + 1568);     // 3072 floats
    float (*ssc)[52]     = (float(*)[52])sbuf;              // 2548 floats (overlays sx/swt)

    __shared__ float sq[WD][HD];      // Q rows
    __shared__ float skT[HD][52];     // K transposed, padded for float4
    __shared__ float sv[WD][HD];      // V rows
    __shared__ float sbias[3 * HD];
    __shared__ float srpb[169];
    __shared__ int   sreg[WD];

    const int tid  = threadIdx.x;
    const int lane = tid & 31;
    const int warp = tid >> 5;

    // ---- preload: x slice (fused shift+partition), weights, bias, rpb, regions ----
    for (int i = tid; i < WD * (HD / 4); i += 256) {      // 392 float4s
        const int t = i >> 3, d4 = i & 7;
        const int tr = t / WS, tcl = t % WS;
        const int gr = (wh * WS + tr + SHIFT) % HH;
        const int gc = (wc * WS + tcl + SHIFT) % WIMG;
        const float4 v = *(const float4*)&x[((size_t)b * NTOK + gr * WIMG + gc) * EMB + h * HD + d4 * 4];
        *(float4*)&sx[t][d4 * 4] = v;
    }
    for (int i = tid; i < HD * 96 / 4; i += 256)          // 768 float4s
        *(float4*)&swt[0][i * 4] = *(const float4*)&qkv_w[i * 4];
    if (tid < 96) sbias[tid] = qkv_b[tid];
    if (tid < 169) srpb[tid] = rpb[tid * NH + h];
    if (tid < WD) {
        const int tr = tid / WS, tcl = tid % WS;
        const int qi = wh * WS + tr, qj = wc * WS + tcl;
        sreg[tid] = (qi < HH - WS ? 0 : (qi < HH - SHIFT ? 1 : 2)) * 3 +
                    (qj < WIMG - WS ? 0 : (qj < WIMG - SHIFT ? 1 : 2));
    }
    __syncthreads();

    // ---- Stage 1: qkv = sx @ swt + bias, scattered into sq / skT / sv ----
    // item = tt * 24 + cg : tt in [0,25) covers rows 2tt,2tt+1 ; cg in [0,24) covers cols 4cg..4cg+3
    for (int it = tid; it < 25 * 24; it += 256) {
        const int tt = it / 24, cg = it % 24;
        const int t0 = 2 * tt;
        const int t1 = (t0 + 1 < WD) ? t0 + 1 : t0;
        float acc[2][4] = {};
#pragma unroll
        for (int k = 0; k < HD; k++) {
            const float a0 = sx[t0][k];
            const float a1 = sx[t1][k];
            const float4 wv = *(const float4*)&swt[k][cg * 4];
            acc[0][0] += a0 * wv.x; acc[0][1] += a0 * wv.y; acc[0][2] += a0 * wv.z; acc[0][3] += a0 * wv.w;
            acc[1][0] += a1 * wv.x; acc[1][1] += a1 * wv.y; acc[1][2] += a1 * wv.z; acc[1][3] += a1 * wv.w;
        }
        const int seg = cg >> 3;                 // 0:Q 1:K 2:V (4-col groups never cross segments)
#pragma unroll
        for (int i = 0; i < 2; i++) {
            const int t = t0 + i;
            if (t >= WD) break;
#pragma unroll
            for (int j = 0; j < 4; j++) {
                const int c  = cg * 4 + j;
                const int cl = c - seg * 32;
                const float val = acc[i][j] + sbias[c];
                if (seg == 0)      sq[t][cl]  = val;
                else if (seg == 1) skT[cl][t] = val;
                else               sv[t][cl]  = val;
            }
        }
    }
    __syncthreads();

    // ---- Stage 2: scores = Q @ K^T * scale + bias + mask  -> ssc (overlays sx/swt) ----
    const float scale = 0.17677669529663687f;   // 1/sqrt(32)
    // item = q2 * 13 + kg : q2 in [0,25), kg in [0,13) covers kk 4kg..4kg+3 (guarded)
    for (int it = tid; it < 25 * 13; it += 256) {
        const int q2 = it / 13, kg = it % 13;
        const int q0 = 2 * q2;
        const int q1 = (q0 + 1 < WD) ? q0 + 1 : q0;
        float acc[2][4] = {};
#pragma unroll
        for (int d = 0; d < HD; d++) {
            const float a0 = sq[q0][d];
            const float a1 = sq[q1][d];
            const float4 kv = *(const float4*)&skT[d][kg * 4];
            acc[0][0] += a0 * kv.x; acc[0][1] += a0 * kv.y; acc[0][2] += a0 * kv.z; acc[0][3] += a0 * kv.w;
            acc[1][0] += a1 * kv.x; acc[1][1] += a1 * kv.y; acc[1][2] += a1 * kv.z; acc[1][3] += a1 * kv.w;
        }
#pragma unroll
        for (int i = 0; i < 2; i++) {
            const int q = q0 + i;
            if (q >= WD) break;
            const int qr = q / WS, qc = q % WS;
            const int rq = sreg[q];
#pragma unroll
            for (int j = 0; j < 4; j++) {
                const int kk = kg * 4 + j;
                if (kk >= WD) continue;
                const int kr = kk / WS, kc = kk % WS;
                float s = acc[i][j] * scale + srpb[(qr - kr + WS - 1) * (2 * WS - 1) + (qc - kc + WS - 1)];
                if (rq != sreg[kk]) s -= 100.f;
                ssc[q][kk] = s;
            }
        }
    }
    __syncthreads();

    // ---- Stage 3: softmax, warp per row ----
    for (int row = warp; row < WD; row += 8) {
        const float v0 = ssc[row][lane];
        const bool has2 = (lane + 32) < WD;
        const float v1 = has2 ? ssc[row][lane + 32] : -1e30f;
        float m = fmaxf(v0, v1);
#pragma unroll
        for (int o = 16; o > 0; o >>= 1) m = fmaxf(m, __shfl_xor_sync(0xffffffffu, m, o));
        const float e0 = __expf(v0 - m);
        const float e1 = has2 ? __expf(v1 - m) : 0.f;
        float s = e0 + e1;
#pragma unroll
        for (int o = 16; o > 0; o >>= 1) s += __shfl_xor_sync(0xffffffffu, s, o);
        const float inv = 1.f / s;
        ssc[row][lane] = e0 * inv;
        if (has2) ssc[row][lane + 32] = e1 * inv;
    }
    __syncthreads();

    // ---- Stage 4: O = attn @ V ; fused reverse partition + reverse shift, STG.128 ----
    // item = tt * 8 + dg : tt in [0,25), dg in [0,8) covers d 4dg..4dg+3
    for (int it = tid; it < 25 * 8; it += 256) {
        const int tt = it / 8, dg = it % 8;
        const int t0 = 2 * tt;
        const int t1 = (t0 + 1 < WD) ? t0 + 1 : t0;
        float acc[2][4] = {};
#pragma unroll 7
        for (int kk = 0; kk < WD; kk++) {
            const float a0 = ssc[t0][kk];
            const float a1 = ssc[t1][kk];
            const float4 vv = *(const float4*)&sv[kk][dg * 4];
            acc[0][0] += a0 * vv.x; acc[0][1] += a0 * vv.y; acc[0][2] += a0 * vv.z; acc[0][3] += a0 * vv.w;
            acc[1][0] += a1 * vv.x; acc[1][1] += a1 * vv.y; acc[1][2] += a1 * vv.z; acc[1][3] += a1 * vv.w;
        }
#pragma unroll
        for (int i = 0; i < 2; i++) {
            const int t = t0 + i;
            if (t >= WD) break;
            const int tr = t / WS, tcl = t % WS;
            const int gr = (wh * WS + tr + SHIFT) % HH;
            const int gc = (wc * WS + tcl + SHIFT) % WIMG;
            float4 o;
            o.x = acc[i][0]; o.y = acc[i][1]; o.z = acc[i][2]; o.w = acc[i][3];
            *(float4*)&g_mid[((size_t)b * NTOK + gr * WIMG + gc) * EMB + h * HD + dg * 4] = o;
        }
    }
}

// ---------------------------------------------------------------------------
// Kernel 2: output projection. out = g_mid @ proj_w + proj_b
// M = 100352, N = K = 256. Tiled 64x64x32, 256 threads, 4x4 register tile.
// ---------------------------------------------------------------------------
__global__ __launch_bounds__(256) void proj_kernel(
    const float* __restrict__ Wp,     // (256, 256)
    const float* __restrict__ bias,   // (256,)
    float* __restrict__ out)
{
    __shared__ float As[64][33];
    __shared__ float Bs[32][64];

    const int m0 = blockIdx.y * 64;
    const int n0 = blockIdx.x * 64;
    const int tid = threadIdx.x;
    const int ty = tid >> 4, tx = tid & 15;

    float acc[4][4] = {};

    const float* __restrict__ A = g_mid;

    for (int k0 = 0; k0 < EMB; k0 += 32) {
        for (int i = tid; i < 64 * 32; i += 256) {
            const int r = i >> 5, c = i & 31;
            As[r][c] = A[(size_t)(m0 + r) * EMB + k0 + c];
        }
        for (int i = tid; i < 32 * 64; i += 256) {
            const int r = i >> 6, c = i & 63;
            Bs[r][c] = Wp[(k0 + r) * EMB + n0 + c];
        }
        __syncthreads();
#pragma unroll
        for (int k = 0; k < 32; k++) {
            const float a0 = As[ty * 4 + 0][k];
            const float a1 = As[ty * 4 + 1][k];
            const float a2 = As[ty * 4 + 2][k];
            const float a3 = As[ty * 4 + 3][k];
            const float4 bv = *(const float4*)&Bs[k][tx * 4];
            acc[0][0] += a0 * bv.x; acc[0][1] += a0 * bv.y; acc[0][2] += a0 * bv.z; acc[0][3] += a0 * bv.w;
            acc[1][0] += a1 * bv.x; acc[1][1] += a1 * bv.y; acc[1][2] += a1 * bv.z; acc[1][3] += a1 * bv.w;
            acc[2][0] += a2 * bv.x; acc[2][1] += a2 * bv.y; acc[2][2] += a2 * bv.z; acc[2][3] += a2 * bv.w;
            acc[3][0] += a3 * bv.x; acc[3][1] += a3 * bv.y; acc[3][2] += a3 * bv.z; acc[3][3] += a3 * bv.w;
        }
        __syncthreads();
    }

    const float4 bb = *(const float4*)&bias[n0 + tx * 4];
#pragma unroll
    for (int i = 0; i < 4; i++) {
        float4 o;
        o.x = acc[i][0] + bb.x;
        o.y = acc[i][1] + bb.y;
        o.z = acc[i][2] + bb.z;
        o.w = acc[i][3] + bb.w;
        *(float4*)&out[(size_t)(m0 + ty * 4 + i) * EMB + n0 + tx * 4] = o;
    }
}

// ---------------------------------------------------------------------------
extern "C" void kernel_launch(void* const* d_in, const int* in_sizes, int n_in,
                              void* d_out, int out_size)
{
    const float* x      = (const float*)d_in[0];
    const float* qkv_w  = (const float*)d_in[1];
    const float* qkv_b  = (const float*)d_in[2];
    const float* proj_w = (const float*)d_in[3];
    const float* proj_b = (const float*)d_in[4];
    const float* rpb    = (const float*)d_in[5];
    float* out = (float*)d_out;

    attn_kernel<<<BATCH * NWIN * NH, 256>>>(x, qkv_w, qkv_b, rpb);

    dim3 grid(EMB / 64, (BATCH * NTOK) / 64);   // (4, 1568)
    proj_kernel<<<grid, 256>>>(proj_w, proj_b, out);
}

// round 9
// speedup vs baseline: 1.8853x; 1.3496x over previous
#include <cuda_runtime.h>
#include <cstdint>

#define BATCH 32
#define HH    56
#define WIMG  56
#define WS    7
#define SHIFT 3
#define NH    8
#define EMB   256
#define HD    32
#define NWIN  64
#define WD    49
#define NTOK  (HH * WIMG)   // 3136

// Scratch for attention output in (B, token, E) layout (reverse-shift already applied).
__device__ float g_mid[(size_t)BATCH * NTOK * EMB];

__device__ __forceinline__ float to_tf32(float x) {
    float y;
    asm("cvt.rna.tf32.f32 %0, %1;" : "=f"(y) : "f"(x));
    return y;
}

__device__ __forceinline__ void mma_tf32(float c[4], const uint4& a, const uint2& b) {
    asm volatile(
        "mma.sync.aligned.m16n8k8.row.col.f32.tf32.tf32.f32 "
        "{%0,%1,%2,%3}, {%4,%5,%6,%7}, {%8,%9}, {%0,%1,%2,%3};\n"
        : "+f"(c[0]), "+f"(c[1]), "+f"(c[2]), "+f"(c[3])
        : "r"(a.x), "r"(a.y), "r"(a.z), "r"(a.w), "r"(b.x), "r"(b.y));
}

// ---------------------------------------------------------------------------
// Kernel 1: fused shifted-window attention, register-tiled (unchanged from R2).
// One block per (batch, window, head). 16384 blocks x 256 threads.
// ---------------------------------------------------------------------------
__global__ __launch_bounds__(256) void attn_kernel(
    const float* __restrict__ x,
    const float* __restrict__ qkv_w,   // (HD, 3*HD) = (32, 96)
    const float* __restrict__ qkv_b,   // (96,)
    const float* __restrict__ rpb)     // (169, NH)
{
    const int blk = blockIdx.x;
    const int h  = blk & 7;
    const int w  = (blk >> 3) & 63;
    const int b  = blk >> 9;
    const int wh = w >> 3;
    const int wc = w & 7;

    __shared__ float sbuf[4640];
    float (*sx)[HD]      = (float(*)[HD])sbuf;
    float (*swt)[96]     = (float(*)[96])(sbuf + 1568);
    float (*ssc)[52]     = (float(*)[52])sbuf;

    __shared__ float sq[WD][HD];
    __shared__ float skT[HD][52];
    __shared__ float sv[WD][HD];
    __shared__ float sbias[3 * HD];
    __shared__ float srpb[169];
    __shared__ int   sreg[WD];

    const int tid  = threadIdx.x;
    const int lane = tid & 31;
    const int warp = tid >> 5;

    for (int i = tid; i < WD * (HD / 4); i += 256) {
        const int t = i >> 3, d4 = i & 7;
        const int tr = t / WS, tcl = t % WS;
        const int gr = (wh * WS + tr + SHIFT) % HH;
        const int gc = (wc * WS + tcl + SHIFT) % WIMG;
        const float4 v = *(const float4*)&x[((size_t)b * NTOK + gr * WIMG + gc) * EMB + h * HD + d4 * 4];
        *(float4*)&sx[t][d4 * 4] = v;
    }
    for (int i = tid; i < HD * 96 / 4; i += 256)
        *(float4*)&swt[0][i * 4] = *(const float4*)&qkv_w[i * 4];
    if (tid < 96) sbias[tid] = qkv_b[tid];
    if (tid < 169) srpb[tid] = rpb[tid * NH + h];
    if (tid < WD) {
        const int tr = tid / WS, tcl = tid % WS;
        const int qi = wh * WS + tr, qj = wc * WS + tcl;
        sreg[tid] = (qi < HH - WS ? 0 : (qi < HH - SHIFT ? 1 : 2)) * 3 +
                    (qj < WIMG - WS ? 0 : (qj < WIMG - SHIFT ? 1 : 2));
    }
    __syncthreads();

    for (int it = tid; it < 25 * 24; it += 256) {
        const int tt = it / 24, cg = it % 24;
        const int t0 = 2 * tt;
        const int t1 = (t0 + 1 < WD) ? t0 + 1 : t0;
        float acc[2][4] = {};
#pragma unroll
        for (int k = 0; k < HD; k++) {
            const float a0 = sx[t0][k];
            const float a1 = sx[t1][k];
            const float4 wv = *(const float4*)&swt[k][cg * 4];
            acc[0][0] += a0 * wv.x; acc[0][1] += a0 * wv.y; acc[0][2] += a0 * wv.z; acc[0][3] += a0 * wv.w;
            acc[1][0] += a1 * wv.x; acc[1][1] += a1 * wv.y; acc[1][2] += a1 * wv.z; acc[1][3] += a1 * wv.w;
        }
        const int seg = cg >> 3;
#pragma unroll
        for (int i = 0; i < 2; i++) {
            const int t = t0 + i;
            if (t >= WD) break;
#pragma unroll
            for (int j = 0; j < 4; j++) {
                const int c  = cg * 4 + j;
                const int cl = c - seg * 32;
                const float val = acc[i][j] + sbias[c];
                if (seg == 0)      sq[t][cl]  = val;
                else if (seg == 1) skT[cl][t] = val;
                else               sv[t][cl]  = val;
            }
        }
    }
    __syncthreads();

    const float scale = 0.17677669529663687f;
    for (int it = tid; it < 25 * 13; it += 256) {
        const int q2 = it / 13, kg = it % 13;
        const int q0 = 2 * q2;
        const int q1 = (q0 + 1 < WD) ? q0 + 1 : q0;
        float acc[2][4] = {};
#pragma unroll
        for (int d = 0; d < HD; d++) {
            const float a0 = sq[q0][d];
            const float a1 = sq[q1][d];
            const float4 kv = *(const float4*)&skT[d][kg * 4];
            acc[0][0] += a0 * kv.x; acc[0][1] += a0 * kv.y; acc[0][2] += a0 * kv.z; acc[0][3] += a0 * kv.w;
            acc[1][0] += a1 * kv.x; acc[1][1] += a1 * kv.y; acc[1][2] += a1 * kv.z; acc[1][3] += a1 * kv.w;
        }
#pragma unroll
        for (int i = 0; i < 2; i++) {
            const int q = q0 + i;
            if (q >= WD) break;
            const int qr = q / WS, qc = q % WS;
            const int rq = sreg[q];
#pragma unroll
            for (int j = 0; j < 4; j++) {
                const int kk = kg * 4 + j;
                if (kk >= WD) continue;
                const int kr = kk / WS, kc = kk % WS;
                float s = acc[i][j] * scale + srpb[(qr - kr + WS - 1) * (2 * WS - 1) + (qc - kc + WS - 1)];
                if (rq != sreg[kk]) s -= 100.f;
                ssc[q][kk] = s;
            }
        }
    }
    __syncthreads();

    for (int row = warp; row < WD; row += 8) {
        const float v0 = ssc[row][lane];
        const bool has2 = (lane + 32) < WD;
        const float v1 = has2 ? ssc[row][lane + 32] : -1e30f;
        float m = fmaxf(v0, v1);
#pragma unroll
        for (int o = 16; o > 0; o >>= 1) m = fmaxf(m, __shfl_xor_sync(0xffffffffu, m, o));
        const float e0 = __expf(v0 - m);
        const float e1 = has2 ? __expf(v1 - m) : 0.f;
        float s = e0 + e1;
#pragma unroll
        for (int o = 16; o > 0; o >>= 1) s += __shfl_xor_sync(0xffffffffu, s, o);
        const float inv = 1.f / s;
        ssc[row][lane] = e0 * inv;
        if (has2) ssc[row][lane + 32] = e1 * inv;
    }
    __syncthreads();

    for (int it = tid; it < 25 * 8; it += 256) {
        const int tt = it / 8, dg = it % 8;
        const int t0 = 2 * tt;
        const int t1 = (t0 + 1 < WD) ? t0 + 1 : t0;
        float acc[2][4] = {};
#pragma unroll 7
        for (int kk = 0; kk < WD; kk++) {
            const float a0 = ssc[t0][kk];
            const float a1 = ssc[t1][kk];
            const float4 vv = *(const float4*)&sv[kk][dg * 4];
            acc[0][0] += a0 * vv.x; acc[0][1] += a0 * vv.y; acc[0][2] += a0 * vv.z; acc[0][3] += a0 * vv.w;
            acc[1][0] += a1 * vv.x; acc[1][1] += a1 * vv.y; acc[1][2] += a1 * vv.z; acc[1][3] += a1 * vv.w;
        }
#pragma unroll
        for (int i = 0; i < 2; i++) {
            const int t = t0 + i;
            if (t >= WD) break;
            const int tr = t / WS, tcl = t % WS;
            const int gr = (wh * WS + tr + SHIFT) % HH;
            const int gc = (wc * WS + tcl + SHIFT) % WIMG;
            float4 o;
            o.x = acc[i][0]; o.y = acc[i][1]; o.z = acc[i][2]; o.w = acc[i][3];
            *(float4*)&g_mid[((size_t)b * NTOK + gr * WIMG + gc) * EMB + h * HD + dg * 4] = o;
        }
    }
}

// ---------------------------------------------------------------------------
// Kernel 2: output projection via tf32 mma.sync.
// out = g_mid @ proj_w + proj_b. M=100352, N=K=256.
// Block 128x128, 8 warps, warp tile 32x64 (2x8 m16n8 tiles), K chunked by 32,
// register prefetch of next chunk, fragment-native smem with XOR swizzle.
// NOTE: g_mid is referenced as a device symbol INSIDE the kernel (passing it
// as a host-side kernel argument hands over the host shadow address — R6 bug).
// ---------------------------------------------------------------------------
__global__ __launch_bounds__(256) void proj_mma_kernel(
    const float* __restrict__ Wp,     // (256, 256) row-major (k, n)
    const float* __restrict__ bias,
    float* __restrict__ out)
{
    const float* __restrict__ A = g_mid;   // device-side symbol reference

    __shared__ float As[8][4][32][4];   // [m16-tile][kstep][lane^ks][reg]
    __shared__ float Bs[16][4][32][2];  // [n8-tile][kstep][lane^nt][reg]
    __shared__ float sb[128];

    const int tid  = threadIdx.x;
    const int lane = tid & 31;
    const int warp = tid >> 5;
    const int wm   = warp >> 1;   // 0..3
    const int wn   = warp & 1;    // 0..1
    const int m0   = blockIdx.y * 128;
    const int n0   = blockIdx.x * 128;

    if (tid < 128) sb[tid] = bias[n0 + tid];

    const int arow = tid >> 3;    // 0..31  (A row base, 4 passes of +32)
    const int akc4 = tid & 7;     // float4 slot in 32-k chunk
    const int bkr  = tid >> 5;    // 0..7   (B k row base, 4 passes of +8)
    const int bnc4 = tid & 31;    // float4 slot in 128-n tile

    float4 ra[4], rb[4];
#pragma unroll
    for (int p = 0; p < 4; p++) {
        ra[p] = *(const float4*)&A[(size_t)(m0 + arow + p * 32) * EMB + akc4 * 4];
        rb[p] = *(const float4*)&Wp[(size_t)(bkr + p * 8) * EMB + n0 + bnc4 * 4];
    }

    float acc[2][8][4];
#pragma unroll
    for (int i = 0; i < 2; i++)
#pragma unroll
        for (int j = 0; j < 8; j++)
#pragma unroll
            for (int r = 0; r < 4; r++) acc[i][j][r] = 0.f;

    for (int c = 0; c < 8; c++) {
        // ---- store prefetched chunk to smem (tf32-converted, fragment layout) ----
#pragma unroll
        for (int p = 0; p < 4; p++) {
            const int row = arow + p * 32;
            const int mt = row >> 4, rit = row & 15;
            const float va[4] = {ra[p].x, ra[p].y, ra[p].z, ra[p].w};
#pragma unroll
            for (int j = 0; j < 4; j++) {
                const int kc = akc4 * 4 + j, ks = kc >> 3, kis = kc & 7;
                const int ls = ((rit & 7) << 2) | (kis & 3);
                const int rg = (rit >> 3) | ((kis >> 2) << 1);
                As[mt][ks][ls ^ ks][rg] = to_tf32(va[j]);
            }
            const int kr = bkr + p * 8;
            const int ksb = kr >> 3, kisb = kr & 7;
            const float vb[4] = {rb[p].x, rb[p].y, rb[p].z, rb[p].w};
#pragma unroll
            for (int j = 0; j < 4; j++) {
                const int n_in = bnc4 * 4 + j;
                const int nt = n_in >> 3, n8 = n_in & 7;
                const int ls = (n8 << 2) | (kisb & 3);
                Bs[nt][ksb][ls ^ nt][kisb >> 2] = to_tf32(vb[j]);
            }
        }
        __syncthreads();

        // ---- prefetch next chunk ----
        if (c < 7) {
            const int k0 = (c + 1) * 32;
#pragma unroll
            for (int p = 0; p < 4; p++) {
                ra[p] = *(const float4*)&A[(size_t)(m0 + arow + p * 32) * EMB + k0 + akc4 * 4];
                rb[p] = *(const float4*)&Wp[(size_t)(k0 + bkr + p * 8) * EMB + n0 + bnc4 * 4];
            }
        }

        // ---- mma over current chunk ----
#pragma unroll
        for (int ks = 0; ks < 4; ks++) {
            uint4 af[2];
#pragma unroll
            for (int mt = 0; mt < 2; mt++)
                af[mt] = *(const uint4*)&As[wm * 2 + mt][ks][lane ^ ks][0];
            uint2 bf[8];
#pragma unroll
            for (int nl = 0; nl < 8; nl++) {
                const int nt = wn * 8 + nl;
                bf[nl] = *(const uint2*)&Bs[nt][ks][lane ^ nt][0];
            }
#pragma unroll
            for (int mt = 0; mt < 2; mt++)
#pragma unroll
                for (int nl = 0; nl < 8; nl++)
                    mma_tf32(acc[mt][nl], af[mt], bf[nl]);
        }
        __syncthreads();
    }

    // ---- epilogue: bias + store (float2 per c-pair) ----
    const int colL_base = wn * 64;
#pragma unroll
    for (int mt = 0; mt < 2; mt++) {
        const int row0 = m0 + wm * 32 + mt * 16 + (lane >> 2);
#pragma unroll
        for (int nl = 0; nl < 8; nl++) {
            const int colL = colL_base + nl * 8 + (lane & 3) * 2;
            const float b0 = sb[colL], b1 = sb[colL + 1];
            float2 v0, v1;
            v0.x = acc[mt][nl][0] + b0; v0.y = acc[mt][nl][1] + b1;
            v1.x = acc[mt][nl][2] + b0; v1.y = acc[mt][nl][3] + b1;
            *(float2*)&out[(size_t)row0 * EMB + n0 + colL] = v0;
            *(float2*)&out[(size_t)(row0 + 8) * EMB + n0 + colL] = v1;
        }
    }
}

// ---------------------------------------------------------------------------
extern "C" void kernel_launch(void* const* d_in, const int* in_sizes, int n_in,
                              void* d_out, int out_size)
{
    const float* x      = (const float*)d_in[0];
    const float* qkv_w  = (const float*)d_in[1];
    const float* qkv_b  = (const float*)d_in[2];
    const float* proj_w = (const float*)d_in[3];
    const float* proj_b = (const float*)d_in[4];
    const float* rpb    = (const float*)d_in[5];
    float* out = (float*)d_out;

    attn_kernel<<<BATCH * NWIN * NH, 256>>>(x, qkv_w, qkv_b, rpb);

    dim3 grid(EMB / 128, (BATCH * NTOK) / 128);   // (2, 784)
    proj_mma_kernel<<<grid, 256>>>(proj_w, proj_b, out);
}

// round 12
// speedup vs baseline: 2.8943x; 1.5352x over previous
#include <cuda_runtime.h>
#include <cstdint>

#define BATCH 32
#define HH    56
#define WIMG  56
#define WS    7
#define SHIFT 3
#define NH    8
#define EMB   256
#define HD    32
#define NWIN  64
#define WD    49
#define NTOK  (HH * WIMG)   // 3136
#define PADX  36            // smem row stride for 32/36-wide tiles
#define PADS  60            // smem row stride for 56-wide tiles

// Scratch for attention output in (B, token, E) layout (reverse-shift already applied).
__device__ float g_mid[(size_t)BATCH * NTOK * EMB];

__device__ __forceinline__ float to_tf32(float x) {
    float y;
    asm("cvt.rna.tf32.f32 %0, %1;" : "=f"(y) : "f"(x));
    return y;
}

__device__ __forceinline__ void mma_tf32(float c[4], const uint4& a, const uint2& b) {
    asm volatile(
        "mma.sync.aligned.m16n8k8.row.col.f32.tf32.tf32.f32 "
        "{%0,%1,%2,%3}, {%4,%5,%6,%7}, {%8,%9}, {%0,%1,%2,%3};\n"
        : "+f"(c[0]), "+f"(c[1]), "+f"(c[2]), "+f"(c[3])
        : "r"(a.x), "r"(a.y), "r"(a.z), "r"(a.w), "r"(b.x), "r"(b.y));
}

// m16n8k8 tf32 fragment loads (mapping silicon-validated by proj kernel in R9):
// A (row-major m,k): a0=(r,c) a1=(r+8,c) a2=(r,c+4) a3=(r+8,c+4), r=lane>>2, c=lane&3
// B ("col" = (n,k) rows): b0=(n,k) b1=(n,k+4), n=lane>>2, k=lane&3
template<int W>
__device__ __forceinline__ uint4 ldAfrag(const float* S, int r0, int c0, int lane) {
    const int r = r0 + (lane >> 2), c = c0 + (lane & 3);
    uint4 a;
    a.x = __float_as_uint(S[r * W + c]);
    a.y = __float_as_uint(S[(r + 8) * W + c]);
    a.z = __float_as_uint(S[r * W + c + 4]);
    a.w = __float_as_uint(S[(r + 8) * W + c + 4]);
    return a;
}
template<int W>
__device__ __forceinline__ uint2 ldBfrag(const float* S, int n0, int k0, int lane) {
    const int n = n0 + (lane >> 2), k = k0 + (lane & 3);
    uint2 b;
    b.x = __float_as_uint(S[n * W + k]);
    b.y = __float_as_uint(S[n * W + k + 4]);
    return b;
}

// ---------------------------------------------------------------------------
// Kernel 1: fused shifted-window attention, all matmuls on tf32 mma.sync.
// One block per (batch, window, head) = 16384 blocks x 256 threads (8 warps).
// Stages: x-gather -> QKV MMA -> scores MMA -> softmax(+bias+mask) -> PV MMA.
// ---------------------------------------------------------------------------
__global__ __launch_bounds__(256) void attn_mma_kernel(
    const float* __restrict__ x,
    const float* __restrict__ qkv_w,   // (32, 96) row-major (k, n)
    const float* __restrict__ qkv_b,   // (96,)
    const float* __restrict__ rpb)     // (169, NH)
{
    const int blk = blockIdx.x;
    const int h  = blk & 7;
    const int w  = (blk >> 3) & 63;
    const int b  = blk >> 9;
    const int wh = w >> 3;
    const int wc = w & 7;

    // Unions: sS (64x60) overlays sX (64x36, dead after QKV MMAs);
    //         sWT (96x36) overlays sVT (32x60, written after QKV MMAs).
    __shared__ float sS[64 * PADS];          // 15360 B
    __shared__ float sWT[96 * PADX];         // 13824 B
    __shared__ float sQ[64 * PADX];          //  9216 B
    __shared__ float sK[56 * PADX];          //  8064 B
    __shared__ float srpb[169];
    __shared__ float sbias[96];
    __shared__ int   sreg[WD];
    float* sX  = sS;                         // 64 x PADX (fits: 36 <= 60 stride-compatible? use own stride)
    float* sVT = sWT;                        // 32 x PADS (7680 B <= 13824)

    const int tid  = threadIdx.x;
    const int lane = tid & 31;
    const int warp = tid >> 5;

    // ---- stage 0: fill smem ----
    // zero x pad rows 49..63 (cols <32 are what fragments read)
    for (int i = tid; i < 15 * PADX; i += 256) sX[49 * PADX + i] = 0.f;
    // gather x (fused cyclic shift + window partition), tf32-convert
    for (int i = tid; i < WD * 8; i += 256) {
        const int t = i >> 3, c4 = i & 7;
        const int tr = t / WS, tcl = t % WS;
        const int gr = (wh * WS + tr + SHIFT) % HH;
        const int gc = (wc * WS + tcl + SHIFT) % WIMG;
        const float4 v = *(const float4*)&x[((size_t)b * NTOK + gr * WIMG + gc) * EMB + h * HD + c4 * 4];
        float* d = &sX[t * PADX + c4 * 4];
        d[0] = to_tf32(v.x); d[1] = to_tf32(v.y); d[2] = to_tf32(v.z); d[3] = to_tf32(v.w);
    }
    // weight transposed: sWT[n][k] = qkv_w[k][n]
    for (int i = tid; i < 96 * 32; i += 256) {
        const int k = i / 96, n = i % 96;
        sWT[n * PADX + k] = to_tf32(qkv_w[k * 96 + n]);
    }
    if (tid < 96)  sbias[tid] = qkv_b[tid];
    if (tid < 169) srpb[tid] = rpb[tid * NH + h];
    if (tid < WD) {
        const int tr = tid / WS, tcl = tid % WS;
        const int qi = wh * WS + tr, qj = wc * WS + tcl;
        sreg[tid] = (qi < HH - WS ? 0 : (qi < HH - SHIFT ? 1 : 2)) * 3 +
                    (qj < WIMG - WS ? 0 : (qj < WIMG - SHIFT ? 1 : 2));
    }
    __syncthreads();

    // ---- stage 1: QKV = sX(64x32) @ W(32x96) ----
    // warp -> m-tile (warp>>1), 6 n-tiles each ((warp&1)*6 ..)
    const int mt  = warp >> 1;
    const int nt0 = (warp & 1) * 6;
    float accQ[6][4];
#pragma unroll
    for (int j = 0; j < 6; j++)
#pragma unroll
        for (int r = 0; r < 4; r++) accQ[j][r] = 0.f;
#pragma unroll
    for (int ks = 0; ks < 4; ks++) {
        const uint4 a = ldAfrag<PADX>(sX, mt * 16, ks * 8, lane);
#pragma unroll
        for (int j = 0; j < 6; j++) {
            const uint2 bf = ldBfrag<PADX>(sWT, (nt0 + j) * 8, ks * 8, lane);
            mma_tf32(accQ[j], a, bf);
        }
    }
    __syncthreads();   // all warps done reading sX / sWT

    // ---- stage 1b: scatter C frags -> sQ / sK / sVT (+bias, tf32, zero-pad) ----
    {
        const int r0 = mt * 16 + (lane >> 2);
        const int r1 = r0 + 8;
#pragma unroll
        for (int j = 0; j < 6; j++) {
            const int nt = nt0 + j;
            const int c0 = nt * 8 + 2 * (lane & 3);
            const int seg = nt >> 2;               // 0:Q 1:K 2:V
            const int cl0 = c0 - seg * 32, cl1 = cl0 + 1;
#pragma unroll
            for (int p = 0; p < 2; p++) {
                const int t = p ? r1 : r0;
                const float v0 = (t < WD) ? to_tf32(accQ[j][p * 2 + 0] + sbias[c0])     : 0.f;
                const float v1 = (t < WD) ? to_tf32(accQ[j][p * 2 + 1] + sbias[c0 + 1]) : 0.f;
                if (seg == 0) {
                    sQ[t * PADX + cl0] = v0; sQ[t * PADX + cl1] = v1;
                } else if (seg == 1) {
                    if (t < 56) { sK[t * PADX + cl0] = v0; sK[t * PADX + cl1] = v1; }
                } else {
                    if (t < 56) { sVT[cl0 * PADS + t] = v0; sVT[cl1 * PADS + t] = v1; }
                }
            }
        }
    }
    __syncthreads();

    // ---- stage 2: scores = Q(64x32) @ K^T (K is (kk,d) = B-operand directly) ----
    const int ns0 = (warp & 1) ? 4 : 0;
    const int nsc = (warp & 1) ? 3 : 4;
    float accS[4][4];
#pragma unroll
    for (int j = 0; j < 4; j++)
#pragma unroll
        for (int r = 0; r < 4; r++) accS[j][r] = 0.f;
#pragma unroll
    for (int ks = 0; ks < 4; ks++) {
        const uint4 a = ldAfrag<PADX>(sQ, mt * 16, ks * 8, lane);
        for (int j = 0; j < nsc; j++) {
            const uint2 bf = ldBfrag<PADX>(sK, (ns0 + j) * 8, ks * 8, lane);
            mma_tf32(accS[j], a, bf);
        }
    }
    // store raw scores (fp32) into sS (overlays dead sX)
    {
        const int r0 = mt * 16 + (lane >> 2);
        for (int j = 0; j < nsc; j++) {
            const int c0 = (ns0 + j) * 8 + 2 * (lane & 3);
            sS[r0 * PADS + c0]           = accS[j][0];
            sS[r0 * PADS + c0 + 1]       = accS[j][1];
            sS[(r0 + 8) * PADS + c0]     = accS[j][2];
            sS[(r0 + 8) * PADS + c0 + 1] = accS[j][3];
        }
    }
    __syncthreads();

    // ---- stage 3: softmax rows<49, fused scale + rpb + mask; write tf32 P ----
    const float scale = 0.17677669529663687f;   // 1/sqrt(32)
    for (int row = warp; row < WD; row += 8) {
        const int qr = row / WS, qc = row % WS;
        const int rq = sreg[row];
        // kk1 = lane (always < 49)
        const int k1r = lane / WS, k1c = lane % WS;
        float s1 = sS[row * PADS + lane] * scale +
                   srpb[(qr - k1r + WS - 1) * (2 * WS - 1) + (qc - k1c + WS - 1)];
        if (rq != sreg[lane]) s1 -= 100.f;
        // kk2 = lane + 32 (valid if < 49)
        const int kk2 = lane + 32;
        const bool v2 = kk2 < WD;
        float s2 = -1e30f;
        if (v2) {
            const int k2r = kk2 / WS, k2c = kk2 % WS;
            s2 = sS[row * PADS + kk2] * scale +
                 srpb[(qr - k2r + WS - 1) * (2 * WS - 1) + (qc - k2c + WS - 1)];
            if (rq != sreg[kk2]) s2 -= 100.f;
        }
        float m = fmaxf(s1, s2);
#pragma unroll
        for (int o = 16; o > 0; o >>= 1) m = fmaxf(m, __shfl_xor_sync(0xffffffffu, m, o));
        const float e1 = __expf(s1 - m);
        const float e2 = v2 ? __expf(s2 - m) : 0.f;
        float sum = e1 + e2;
#pragma unroll
        for (int o = 16; o > 0; o >>= 1) sum += __shfl_xor_sync(0xffffffffu, sum, o);
        const float inv = 1.f / sum;
        sS[row * PADS + lane] = to_tf32(e1 * inv);
        if (kk2 < 56) sS[row * PADS + kk2] = v2 ? to_tf32(e2 * inv) : 0.f;  // zero pad cols 49..55
    }
    __syncthreads();
    // note: sS rows 49..63 hold raw scores from zeroed Q rows = 0.0 (finite, outputs discarded)

    // ---- stage 4: O = P(64x56) @ V ; B-operand = V^T (d, kk) ----
    const int np0 = (warp & 1) * 2;
    float accP[2][4];
#pragma unroll
    for (int j = 0; j < 2; j++)
#pragma unroll
        for (int r = 0; r < 4; r++) accP[j][r] = 0.f;
#pragma unroll
    for (int ks = 0; ks < 7; ks++) {
        const uint4 a = ldAfrag<PADS>(sS, mt * 16, ks * 8, lane);
#pragma unroll
        for (int j = 0; j < 2; j++) {
            const uint2 bf = ldBfrag<PADS>(sVT, (np0 + j) * 8, ks * 8, lane);
            mma_tf32(accP[j], a, bf);
        }
    }
    // ---- epilogue: fused reverse partition + reverse shift, float2 stores ----
    {
        const int r0 = mt * 16 + (lane >> 2);
#pragma unroll
        for (int j = 0; j < 2; j++) {
            const int c0 = (np0 + j) * 8 + 2 * (lane & 3);
#pragma unroll
            for (int p = 0; p < 2; p++) {
                const int t = r0 + p * 8;
                if (t < WD) {
                    const int tr = t / WS, tcl = t % WS;
                    const int gr = (wh * WS + tr + SHIFT) % HH;
                    const int gc = (wc * WS + tcl + SHIFT) % WIMG;
                    float2 v;
                    v.x = accP[j][p * 2 + 0];
                    v.y = accP[j][p * 2 + 1];
                    *(float2*)&g_mid[((size_t)b * NTOK + gr * WIMG + gc) * EMB + h * HD + c0] = v;
                }
            }
        }
    }
}

// ---------------------------------------------------------------------------
// Kernel 2: output projection via tf32 mma.sync. out = g_mid @ proj_w + proj_b.
// M=100352, N=K=256. Block 128x128, warp tile 32x64. No register prefetch;
// __launch_bounds__(256,2) forces 2 CTAs/SM to hide load latency instead.
// ---------------------------------------------------------------------------
__global__ __launch_bounds__(256, 2) void proj_mma_kernel(
    const float* __restrict__ Wp,     // (256, 256) row-major (k, n)
    const float* __restrict__ bias,
    float* __restrict__ out)
{
    const float* __restrict__ A = g_mid;   // device-side symbol reference

    __shared__ float As[8][4][32][4];   // [m16-tile][kstep][lane^ks][reg]
    __shared__ float Bs[16][4][32][2];  // [n8-tile][kstep][lane^nt][reg]
    __shared__ float sb[128];

    const int tid  = threadIdx.x;
    const int lane = tid & 31;
    const int warp = tid >> 5;
    const int wm   = warp >> 1;   // 0..3
    const int wn   = warp & 1;    // 0..1
    const int m0   = blockIdx.y * 128;
    const int n0   = blockIdx.x * 128;

    if (tid < 128) sb[tid] = bias[n0 + tid];

    const int arow = tid >> 3;    // 0..31  (A row base, 4 passes of +32)
    const int akc4 = tid & 7;     // float4 slot in 32-k chunk
    const int bkr  = tid >> 5;    // 0..7   (B k row base, 4 passes of +8)
    const int bnc4 = tid & 31;    // float4 slot in 128-n tile

    float acc[2][8][4];
#pragma unroll
    for (int i = 0; i < 2; i++)
#pragma unroll
        for (int j = 0; j < 8; j++)
#pragma unroll
            for (int r = 0; r < 4; r++) acc[i][j][r] = 0.f;

    for (int c = 0; c < 8; c++) {
        const int k0 = c * 32;
#pragma unroll
        for (int p = 0; p < 4; p++) {
            const float4 ra = *(const float4*)&A[(size_t)(m0 + arow + p * 32) * EMB + k0 + akc4 * 4];
            const float4 rb = *(const float4*)&Wp[(size_t)(k0 + bkr + p * 8) * EMB + n0 + bnc4 * 4];
            const int row = arow + p * 32;
            const int mt = row >> 4, rit = row & 15;
            const float va[4] = {ra.x, ra.y, ra.z, ra.w};
#pragma unroll
            for (int j = 0; j < 4; j++) {
                const int kc = akc4 * 4 + j, ks = kc >> 3, kis = kc & 7;
                const int ls = ((rit & 7) << 2) | (kis & 3);
                const int rg = (rit >> 3) | ((kis >> 2) << 1);
                As[mt][ks][ls ^ ks][rg] = to_tf32(va[j]);
            }
            const int kr = bkr + p * 8;
            const int ksb = kr >> 3, kisb = kr & 7;
            const float vb[4] = {rb.x, rb.y, rb.z, rb.w};
#pragma unroll
            for (int j = 0; j < 4; j++) {
                const int n_in = bnc4 * 4 + j;
                const int nt = n_in >> 3, n8 = n_in & 7;
                const int ls = (n8 << 2) | (kisb & 3);
                Bs[nt][ksb][ls ^ nt][kisb >> 2] = to_tf32(vb[j]);
            }
        }
        __syncthreads();

#pragma unroll
        for (int ks = 0; ks < 4; ks++) {
            uint4 af[2];
#pragma unroll
            for (int mt = 0; mt < 2; mt++)
                af[mt] = *(const uint4*)&As[wm * 2 + mt][ks][lane ^ ks][0];
            uint2 bf[8];
#pragma unroll
            for (int nl = 0; nl < 8; nl++) {
                const int nt = wn * 8 + nl;
                bf[nl] = *(const uint2*)&Bs[nt][ks][lane ^ nt][0];
            }
#pragma unroll
            for (int mt = 0; mt < 2; mt++)
#pragma unroll
                for (int nl = 0; nl < 8; nl++)
                    mma_tf32(acc[mt][nl], af[mt], bf[nl]);
        }
        __syncthreads();
    }

    // ---- epilogue: bias + store (float2 per c-pair) ----
    const int colL_base = wn * 64;
#pragma unroll
    for (int mt = 0; mt < 2; mt++) {
        const int row0 = m0 + wm * 32 + mt * 16 + (lane >> 2);
#pragma unroll
        for (int nl = 0; nl < 8; nl++) {
            const int colL = colL_base + nl * 8 + (lane & 3) * 2;
            const float b0 = sb[colL], b1 = sb[colL + 1];
            float2 v0, v1;
            v0.x = acc[mt][nl][0] + b0; v0.y = acc[mt][nl][1] + b1;
            v1.x = acc[mt][nl][2] + b0; v1.y = acc[mt][nl][3] + b1;
            *(float2*)&out[(size_t)row0 * EMB + n0 + colL] = v0;
            *(float2*)&out[(size_t)(row0 + 8) * EMB + n0 + colL] = v1;
        }
    }
}

// ---------------------------------------------------------------------------
extern "C" void kernel_launch(void* const* d_in, const int* in_sizes, int n_in,
                              void* d_out, int out_size)
{
    const float* x      = (const float*)d_in[0];
    const float* qkv_w  = (const float*)d_in[1];
    const float* qkv_b  = (const float*)d_in[2];
    const float* proj_w = (const float*)d_in[3];
    const float* proj_b = (const float*)d_in[4];
    const float* rpb    = (const float*)d_in[5];
    float* out = (float*)d_out;

    attn_mma_kernel<<<BATCH * NWIN * NH, 256>>>(x, qkv_w, qkv_b, rpb);

    dim3 grid(EMB / 128, (BATCH * NTOK) / 128);   // (2, 784)
    proj_mma_kernel<<<grid, 256>>>(proj_w, proj_b, out);
}